// round 13
// baseline (speedup 1.0000x reference)
#include <cuda_runtime.h>

#define NB   32
#define CC   512
#define LL   512
#define KG   10
#define VK   8

typedef unsigned long long u64;

// Scratch (no allocations allowed)
__device__ u64   g_a   [NB * 4 * LL];         // assignments as k-pair planes [n][kp][l]
__device__ float g_asum[NB * 8 * VK];         // per-l-tile assign_sum partials
__device__ float g_axp [NB * VK * CC];        // assign_x [n][k][c]
__device__ int   g_ctr [NB];                  // arrival counters (zero-init, self-resetting)

__device__ __forceinline__ u64 pack2(float lo, float hi) {
    u64 r; asm("mov.b64 %0,{%1,%2};" : "=l"(r) : "f"(lo), "f"(hi)); return r;
}
__device__ __forceinline__ void unpack2(u64 v, float& lo, float& hi) {
    asm("mov.b64 {%0,%1},%2;" : "=f"(lo), "=f"(hi) : "l"(v));
}
__device__ __forceinline__ u64 ffma2(u64 a, u64 b, u64 c) {
    u64 d; asm("fma.rn.f32x2 %0,%1,%2,%3;" : "=l"(d) : "l"(a), "l"(b), "l"(c)); return d;
}

// ---------------------------------------------------------------------------
// KA: logits + softmax + a + assign_sum partials, fused. (unchanged, proven)
// grid (L/64, N), block 256.
// ---------------------------------------------------------------------------
__global__ __launch_bounds__(256) void ka_logits_softmax(
    const float* __restrict__ x, const float* __restrict__ w,
    const float* __restrict__ b)
{
    __shared__ float wsh[CC * 12];        // 24 KB, [c][k] 12-padded
    __shared__ float psh[8 * KG * 64];    // 20 KB, [warp][k][l_local]
    __shared__ float red[2][VK];

    const int tid   = threadIdx.x;
    const int lane  = tid & 31;
    const int warp  = tid >> 5;
    const int n     = blockIdx.y;
    const int lbase = blockIdx.x * 64;

    for (int i = tid; i < KG * CC; i += 256) {
        int k = i >> 9, c = i & (CC - 1);
        wsh[c * 12 + k] = w[i];
    }
    __syncthreads();

    u64 accA[5], accB[5];
#pragma unroll
    for (int p = 0; p < 5; p++) { accA[p] = 0ull; accB[p] = 0ull; }

    const int c0 = warp * 64;
    const float* xp = x + ((size_t)n * CC + c0) * LL + lbase + lane * 2;
#pragma unroll 1
    for (int cb = 0; cb < 64; cb += 16) {
        const float* xc = xp + (size_t)cb * LL;
        float2 xv[16];
#pragma unroll
        for (int i = 0; i < 16; i++) xv[i] = *(const float2*)(xc + i * LL);
#pragma unroll
        for (int i = 0; i < 16; i++) {
            u64 xa = pack2(xv[i].x, xv[i].x);
            u64 xb = pack2(xv[i].y, xv[i].y);
            const float* wr = wsh + (c0 + cb + i) * 12;
            u64 w0 = *(const u64*)(wr + 0);
            u64 w1 = *(const u64*)(wr + 2);
            u64 w2 = *(const u64*)(wr + 4);
            u64 w3 = *(const u64*)(wr + 6);
            u64 w4 = *(const u64*)(wr + 8);
            accA[0] = ffma2(w0, xa, accA[0]);  accB[0] = ffma2(w0, xb, accB[0]);
            accA[1] = ffma2(w1, xa, accA[1]);  accB[1] = ffma2(w1, xb, accB[1]);
            accA[2] = ffma2(w2, xa, accA[2]);  accB[2] = ffma2(w2, xb, accB[2]);
            accA[3] = ffma2(w3, xa, accA[3]);  accB[3] = ffma2(w3, xb, accB[3]);
            accA[4] = ffma2(w4, xa, accA[4]);  accB[4] = ffma2(w4, xb, accB[4]);
        }
    }

    {
        float lgA[KG], lgB[KG];
#pragma unroll
        for (int p = 0; p < 5; p++) {
            unpack2(accA[p], lgA[2 * p], lgA[2 * p + 1]);
            unpack2(accB[p], lgB[2 * p], lgB[2 * p + 1]);
        }
        float* pr = psh + (warp * KG) * 64 + lane * 2;
#pragma unroll
        for (int k = 0; k < KG; k++) {
            float2 v; v.x = lgA[k]; v.y = lgB[k];
            *(float2*)(pr + k * 64) = v;
        }
    }
    __syncthreads();

    if (tid < 64) {
        float lg[KG];
#pragma unroll
        for (int k = 0; k < KG; k++) lg[k] = __ldg(b + k);
#pragma unroll
        for (int wp = 0; wp < 8; wp++) {
            const float* pr = psh + (wp * KG) * 64 + tid;
#pragma unroll
            for (int k = 0; k < KG; k++) lg[k] += pr[k * 64];
        }

        float m = lg[0];
#pragma unroll
        for (int k = 1; k < KG; k++) m = fmaxf(m, lg[k]);
        float s = 0.f;
#pragma unroll
        for (int k = 0; k < KG; k++) { lg[k] = __expf(lg[k] - m); s += lg[k]; }
        float inv = 1.f / s;

#pragma unroll
        for (int k = 0; k < VK; k++) lg[k] *= inv;

        // a as k-pair planes [n][kp][l]: 4 coalesced STG.64
        u64* ap = g_a + (size_t)n * 4 * LL + lbase + tid;
#pragma unroll
        for (int kp = 0; kp < 4; kp++)
            ap[kp * LL] = pack2(lg[2 * kp], lg[2 * kp + 1]);

#pragma unroll
        for (int o = 4; o >= 1; o >>= 1) {
            bool up = (lane & o) != 0;
#pragma unroll
            for (int i = 0; i < 8; i++) {
                if (i < o) {
                    float keep = up ? lg[i + o] : lg[i];
                    float send = up ? lg[i] : lg[i + o];
                    lg[i] = keep + __shfl_xor_sync(0xffffffffu, send, o);
                }
            }
        }
        float t0 = lg[0];
        t0 += __shfl_xor_sync(0xffffffffu, t0, 8);
        t0 += __shfl_xor_sync(0xffffffffu, t0, 16);
        if (lane < 8) red[warp][lane] = t0;
    }
    __syncthreads();
    if (tid < VK)
        g_asum[((size_t)n * 8 + blockIdx.x) * VK + tid] = red[0][tid] + red[1][tid];
}

// ---------------------------------------------------------------------------
// KB: streaming-copy x slice to smem with FORCED 16-deep LDG batch (reg
// budget 128 via launch_bounds(256,2) + compiler barrier so ptxas cannot
// fold loads into load/store pairs). Compute assign_x from smem only.
// grid (C/32, N), block 256, dynamic smem 80 KB (2 CTAs/SM).
// Last block per n runs the epilogue.
// ---------------------------------------------------------------------------
#define KB_DYN_BYTES (16384 * 4 + 2048 * 8)          // 64 KB x slice + 16 KB a planes

__global__ __launch_bounds__(256, 2) void kb_assign_epilogue(
    const float* __restrict__ x, const float* __restrict__ centers,
    float* __restrict__ out)
{
    extern __shared__ __align__(16) float dyn[];
    float* xs = dyn;                    // 16384 floats: [c_local][l]
    u64*   as8 = (u64*)(dyn + 16384);   // 2048 u64: [kp][l]

    __shared__ float asum_sh[VK];
    __shared__ float red2[8][VK];
    __shared__ float scale_sh[VK];
    __shared__ int   is_last;

    const int tid  = threadIdx.x;
    const int lane = tid & 31;
    const int warp = tid >> 5;
    const int n    = blockIdx.y;
    const int c0b  = blockIdx.x * 32;

    // ---- Phase 1: streaming copy, 16 LDG.128 guaranteed in flight ----
    {
        const float4* xg = (const float4*)(x + ((size_t)n * CC + c0b) * LL);
        float4* xd = (float4*)xs;
        float4 t[16];
#pragma unroll
        for (int i = 0; i < 16; i++) t[i] = xg[tid + i * 256];
        asm volatile("" ::: "memory");   // all 16 loads issued before any store
#pragma unroll
        for (int i = 0; i < 16; i++) xd[tid + i * 256] = t[i];

        const u64* ag = g_a + (size_t)n * 4 * LL;
        u64 ta[8];
#pragma unroll
        for (int i = 0; i < 8; i++) ta[i] = ag[tid + i * 256];
        asm volatile("" ::: "memory");
#pragma unroll
        for (int i = 0; i < 8; i++) as8[tid + i * 256] = ta[i];
    }
    __syncthreads();

    // ---- Phase 2: compute from smem only ----
    const int cw = warp * 4;   // warp's 4 local c rows

    u64 acc[4][4];
#pragma unroll
    for (int ci = 0; ci < 4; ci++)
#pragma unroll
        for (int kp = 0; kp < 4; kp++) acc[ci][kp] = 0ull;

#pragma unroll
    for (int j = 0; j < 16; j++) {
        const int l = j * 32 + lane;
        u64 a2[4];
#pragma unroll
        for (int kp = 0; kp < 4; kp++) a2[kp] = as8[kp * LL + l];
        float xv[4];
#pragma unroll
        for (int ci = 0; ci < 4; ci++) xv[ci] = xs[(cw + ci) * LL + l];
#pragma unroll
        for (int ci = 0; ci < 4; ci++) {
            u64 xd = pack2(xv[ci], xv[ci]);
#pragma unroll
            for (int kp = 0; kp < 4; kp++)
                acc[ci][kp] = ffma2(a2[kp], xd, acc[ci][kp]);
        }
    }

    // 32 outputs per thread -> butterfly reduce-scatter: lane L keeps v[L]
    {
        float v[32];
#pragma unroll
        for (int ci = 0; ci < 4; ci++)
#pragma unroll
            for (int kp = 0; kp < 4; kp++)
                unpack2(acc[ci][kp], v[ci * 8 + 2 * kp], v[ci * 8 + 2 * kp + 1]);

#pragma unroll
        for (int o = 16; o >= 1; o >>= 1) {
            bool up = (lane & o) != 0;
#pragma unroll
            for (int i = 0; i < 32; i++) {
                if (i < o) {
                    float keep = up ? v[i + o] : v[i];
                    float send = up ? v[i] : v[i + o];
                    v[i] = keep + __shfl_xor_sync(0xffffffffu, send, o);
                }
            }
        }

        int ci = lane >> 3, k = lane & 7;
        g_axp[((size_t)n * VK + k) * CC + c0b + cw + ci] = v[0];
    }

    // ---- arrival: 16th block for this n runs the epilogue ----
    __syncthreads();
    if (tid == 0) {
        __threadfence();
        int old = atomicAdd(&g_ctr[n], 1);
        is_last = (old == 15);
    }
    __syncthreads();
    if (!is_last) return;
    __threadfence();

    if (tid < VK) {
        float s = 0.f;
#pragma unroll
        for (int blk = 0; blk < 8; blk++)
            s += g_asum[((size_t)n * 8 + blk) * VK + tid];
        asum_sh[tid] = s;
    }
    __syncthreads();

    // residuals -> xs (reg-light cold path); thread owns c = tid, tid+256
    float sq[VK];
#pragma unroll
    for (int k = 0; k < VK; k++) {
        const float* axr = g_axp + ((size_t)n * VK + k) * CC;
        const float* cr  = centers + k * CC;
        float rA = axr[tid]       - asum_sh[k] * cr[tid];
        float rB = axr[tid + 256] - asum_sh[k] * cr[tid + 256];
        xs[k * CC + tid]       = rA;
        xs[k * CC + tid + 256] = rB;
        sq[k] = rA * rA + rB * rB;
    }

    // octet reduce-scatter within warp, then cross-warp via smem
#pragma unroll
    for (int o = 4; o >= 1; o >>= 1) {
        bool up = (lane & o) != 0;
#pragma unroll
        for (int i = 0; i < 8; i++) {
            if (i < o) {
                float keep = up ? sq[i + o] : sq[i];
                float send = up ? sq[i] : sq[i + o];
                sq[i] = keep + __shfl_xor_sync(0xffffffffu, send, o);
            }
        }
    }
    {
        float t0 = sq[0];
        t0 += __shfl_xor_sync(0xffffffffu, t0, 8);
        t0 += __shfl_xor_sync(0xffffffffu, t0, 16);
        if (lane < 8) red2[warp][lane] = t0;
    }
    __syncthreads();

    if (warp == 0) {
        int k = lane & 7;
        float ss = 0.f;
#pragma unroll
        for (int wp = 0; wp < 8; wp++) ss += red2[wp][k];
        float s1 = 1.f / fmaxf(sqrtf(ss), 1e-12f);
        float vlad = ss * s1 * s1;
        vlad += __shfl_xor_sync(0xffffffffu, vlad, 4);
        vlad += __shfl_xor_sync(0xffffffffu, vlad, 2);
        vlad += __shfl_xor_sync(0xffffffffu, vlad, 1);
        float fs = 1.f / fmaxf(sqrtf(vlad), 1e-12f);
        if (lane < 8) scale_sh[k] = s1 * fs;
    }
    __syncthreads();

#pragma unroll
    for (int k = 0; k < VK; k++) {
        float* o = out + (size_t)n * VK * CC + k * CC;
        o[tid]       = xs[k * CC + tid]       * scale_sh[k];
        o[tid + 256] = xs[k * CC + tid + 256] * scale_sh[k];
    }

    if (tid == 0) g_ctr[n] = 0;   // re-arm for next replay
}

// ---------------------------------------------------------------------------
extern "C" void kernel_launch(void* const* d_in, const int* in_sizes, int n_in,
                              void* d_out, int out_size)
{
    const float* x       = (const float*)d_in[0];  // [32,512,16,32]
    const float* conv_w  = (const float*)d_in[1];  // [10,512]
    const float* conv_b  = (const float*)d_in[2];  // [10]
    const float* centers = (const float*)d_in[3];  // [10,512]
    float* out = (float*)d_out;                    // [32, 4096]

    cudaFuncSetAttribute(kb_assign_epilogue,
                         cudaFuncAttributeMaxDynamicSharedMemorySize, KB_DYN_BYTES);

    ka_logits_softmax <<<dim3(LL / 64, NB), 256>>>(x, conv_w, conv_b);
    kb_assign_epilogue<<<dim3(CC / 32, NB), 256, KB_DYN_BYTES>>>(x, centers, out);
}